// round 1
// baseline (speedup 1.0000x reference)
#include <cuda_runtime.h>
#include <cuda_bf16.h>

// Problem constants (fixed shapes)
#define SIGMA   16
#define PATCH   33          // 2*SIGMA+1
#define HW      256
#define BATCH   4
#define KPTS    64
#define NKP     256         // BATCH*KPTS keypoints per side
#define NPATCH  1024        // NKP*BATCH patches per side
#define C1      32
#define C1H     31          // conv1 output spatial
#define C2      64
#define C2H     15          // conv2 output spatial (stride 2, VALID)
#define OUTF    128

// smem layout (floats):
//   [0, 30752)                   conv1 output  (32*31*31)
//   [30752, 30752+18432)         overlay: {patch(3267)+w1(864)} then w2(18432)
//   [49184, 49184+960)           per-row conv2 sums (64*15)
#define SM_C1     (C1*C1H*C1H)          // 30752
#define SM_OVER   (C2*C1*9)             // 18432  (>= 3267+864)
#define SM_ROWS   (C2*C2H)              // 960
#define SM_TOTAL  (SM_C1 + SM_OVER + SM_ROWS)   // 50144 floats = 200576 B

// Scratch (device globals — no allocation allowed)
__device__ float g_h[2 * NPATCH * C2];      // GAP features, [set][n*4+b][64]
__device__ float g_pairsum[NPATCH];         // per-pair sum of squared projected diff

// ---------------------------------------------------------------------------
// Kernel A: per-patch CNN up to GAP. One block per patch.
// blockIdx.x in [0,2048): set = bid>>10, m = bid&1023, n = m>>2, b = m&3
// ---------------------------------------------------------------------------
__global__ void __launch_bounds__(512, 1)
patch_cnn_kernel(const float* __restrict__ img_g, const float* __restrict__ img_s,
                 const float* __restrict__ kp_g,  const float* __restrict__ kp_s,
                 const float* __restrict__ w1,    const float* __restrict__ b1,
                 const float* __restrict__ w2,    const float* __restrict__ b2)
{
    extern __shared__ float sm[];
    float* c1     = sm;                       // 30752
    float* ov     = sm + SM_C1;               // overlay region
    float* patch  = ov;                       // 3*33*33 = 3267
    float* w1s    = ov + 3 * PATCH * PATCH;   // 864
    float* w2s    = ov;                       // 18432 (after conv1)
    float* rowsum = sm + SM_C1 + SM_OVER;     // 960

    const int p   = blockIdx.x;
    const int set = p >> 10;
    const int m   = p & 1023;
    const int n   = m >> 2;
    const int b   = m & 3;
    const float* img = set ? img_s : img_g;
    const float* kp  = set ? kp_s  : kp_g;

    const float px = kp[2 * n]     * (float)HW;
    const float py = kp[2 * n + 1] * (float)HW;
    int sx = (int)floorf(px) - SIGMA;
    int sy = (int)floorf(py) - SIGMA;
    sx = min(max(sx, 0), HW - PATCH);
    sy = min(max(sy, 0), HW - PATCH);

    const int tid = threadIdx.x;
    const int nthr = blockDim.x;

    // ---- stage patch + w1 ----
    for (int i = tid; i < 3 * PATCH * PATCH; i += nthr) {
        int ic = i / (PATCH * PATCH);
        int r  = i % (PATCH * PATCH);
        int y  = r / PATCH, x = r % PATCH;
        patch[i] = img[(((size_t)b * 3 + ic) * HW + (sy + y)) * HW + (sx + x)];
    }
    for (int i = tid; i < C1 * 3 * 9; i += nthr) w1s[i] = w1[i];
    __syncthreads();

    // ---- conv1 (3->32, 3x3, VALID, s1) + bias + relu ----
    for (int idx = tid; idx < C1 * C1H * C1H; idx += nthr) {
        int oc = idx / (C1H * C1H);
        int r  = idx % (C1H * C1H);
        int y  = r / C1H, x = r % C1H;
        float acc = b1[oc];
        const float* wb = &w1s[oc * 27];
        #pragma unroll
        for (int ic = 0; ic < 3; ic++)
            #pragma unroll
            for (int ky = 0; ky < 3; ky++)
                #pragma unroll
                for (int kx = 0; kx < 3; kx++)
                    acc += patch[(ic * PATCH + y + ky) * PATCH + x + kx] *
                           wb[(ic * 3 + ky) * 3 + kx];
        c1[idx] = fmaxf(acc, 0.0f);
    }
    __syncthreads();

    // ---- stage w2 (overwrites patch/w1) ----
    for (int i = tid; i < C2 * C1 * 9; i += nthr) w2s[i] = w2[i];
    __syncthreads();

    // ---- conv2 (32->64, 3x3, VALID, s2) + bias + relu, row-wise, + row sums ----
    for (int row = tid; row < C2 * C2H; row += nthr) {
        int oc2 = row / C2H;
        int oy  = row % C2H;
        float acc[C2H];
        float bb = b2[oc2];
        #pragma unroll
        for (int i = 0; i < C2H; i++) acc[i] = bb;

        for (int ic = 0; ic < C1; ic++) {
            #pragma unroll
            for (int ky = 0; ky < 3; ky++) {
                const float* rp = &c1[(ic * C1H + 2 * oy + ky) * C1H];
                const float* wp = &w2s[((oc2 * C1 + ic) * 3 + ky) * 3];
                float wv0 = wp[0], wv1 = wp[1], wv2 = wp[2];
                float rbuf[C1H];
                #pragma unroll
                for (int i = 0; i < C1H; i++) rbuf[i] = rp[i];
                #pragma unroll
                for (int ox = 0; ox < C2H; ox++)
                    acc[ox] += rbuf[2 * ox] * wv0 + rbuf[2 * ox + 1] * wv1 +
                               rbuf[2 * ox + 2] * wv2;
            }
        }
        float s = 0.0f;
        #pragma unroll
        for (int ox = 0; ox < C2H; ox++) s += fmaxf(acc[ox], 0.0f);
        rowsum[row] = s;
    }
    __syncthreads();

    // ---- GAP (deterministic: thread oc sums its 15 rows) ----
    if (tid < C2) {
        float s = 0.0f;
        #pragma unroll
        for (int oy = 0; oy < C2H; oy++) s += rowsum[tid * C2H + oy];
        g_h[((size_t)set * NPATCH + m) * C2 + tid] = s * (1.0f / 225.0f);
    }
}

// ---------------------------------------------------------------------------
// Kernel B: per-pair projected squared difference.
// d = hg - hs (64), y = wl @ d (128), pairsum = sum(y^2). bl cancels exactly.
// ---------------------------------------------------------------------------
__global__ void __launch_bounds__(128)
pair_kernel(const float* __restrict__ wl)
{
    __shared__ float d[C2];
    __shared__ float red[OUTF];
    const int pair = blockIdx.x;
    const int tid  = threadIdx.x;

    const float* hg = &g_h[(size_t)pair * C2];
    const float* hs = &g_h[((size_t)NPATCH + pair) * C2];
    if (tid < C2) d[tid] = hg[tid] - hs[tid];
    __syncthreads();

    float y = 0.0f;
    const float* wr = &wl[tid * C2];
    #pragma unroll
    for (int i = 0; i < C2; i++) y += wr[i] * d[i];
    red[tid] = y * y;
    __syncthreads();
    #pragma unroll
    for (int s = OUTF / 2; s > 0; s >>= 1) {
        if (tid < s) red[tid] += red[tid + s];
        __syncthreads();
    }
    if (tid == 0) g_pairsum[pair] = red[0];
}

// ---------------------------------------------------------------------------
// Kernel C: final deterministic reduction + mean.
// ---------------------------------------------------------------------------
__global__ void __launch_bounds__(256)
reduce_kernel(float* __restrict__ out)
{
    __shared__ float red[256];
    const int tid = threadIdx.x;
    float s = 0.0f;
    for (int i = tid; i < NPATCH; i += 256) s += g_pairsum[i];
    red[tid] = s;
    __syncthreads();
    #pragma unroll
    for (int st = 128; st > 0; st >>= 1) {
        if (tid < st) red[tid] += red[tid + st];
        __syncthreads();
    }
    if (tid == 0)
        out[0] = red[0] / (float)((size_t)NPATCH * OUTF);  // mean over N*B*OUT
}

// ---------------------------------------------------------------------------
extern "C" void kernel_launch(void* const* d_in, const int* in_sizes, int n_in,
                              void* d_out, int out_size)
{
    const float* img_g = (const float*)d_in[0];
    const float* img_s = (const float*)d_in[1];
    const float* kp_g  = (const float*)d_in[2];
    const float* kp_s  = (const float*)d_in[3];
    const float* w1    = (const float*)d_in[4];
    const float* b1    = (const float*)d_in[5];
    const float* w2    = (const float*)d_in[6];
    const float* b2    = (const float*)d_in[7];
    const float* wl    = (const float*)d_in[8];
    // d_in[9] = bl (cancels in fg - fs), d_in[10] = num_samples (fixed shape)

    const int smem_bytes = SM_TOTAL * (int)sizeof(float);
    cudaFuncSetAttribute(patch_cnn_kernel,
                         cudaFuncAttributeMaxDynamicSharedMemorySize, smem_bytes);

    patch_cnn_kernel<<<2 * NPATCH, 512, smem_bytes>>>(img_g, img_s, kp_g, kp_s,
                                                      w1, b1, w2, b2);
    pair_kernel<<<NPATCH, 128>>>(wl);
    reduce_kernel<<<1, 256>>>((float*)d_out);
}

// round 2
// speedup vs baseline: 2.3834x; 2.3834x over previous
#include <cuda_runtime.h>
#include <cuda_bf16.h>

// Fixed problem shapes
#define SIGMA   16
#define PATCH   33
#define HW      256
#define NPATCH  1024        // N(256) * B(4) per side
#define C1      32
#define C1H     31
#define C2      64
#define C2H     15
#define OUTF    128

// Padded layouts (floats)
#define PROW    36                       // patch row pad (33 -> 36, 16B-align)
#define PPL     (PATCH * PROW)           // 1188 per input channel
#define NPAT    (3 * PPL)                // 3564
#define C1ROW   32                       // c1 row pad (31 -> 32)
#define C1PL    (C1H * C1ROW)            // 992 per channel
#define SM_C1   (C1 * C1PL)              // 31744
#define W1T_SZ  (C1 * 27)                // 864
#define W2T_SZ  (C2 * C1 * 9)            // 18432
#define SM_PART (C2 * 30)                // 1920
// smem: [c1p 31744][overlay: {patch 3564 + w1t 864} then w2t 18432][partial 1920]
#define SM_TOTAL (SM_C1 + W2T_SZ + SM_PART)   // 52096 floats = 208384 B

__device__ float g_h[2 * NPATCH * C2];
__device__ float g_pairsum[NPATCH];

// ---------------------------------------------------------------------------
// Kernel A: per-patch CNN up to GAP. One block per patch (2048 blocks x 512).
// ---------------------------------------------------------------------------
__global__ void __launch_bounds__(512, 1)
patch_cnn_kernel(const float* __restrict__ img_g, const float* __restrict__ img_s,
                 const float* __restrict__ kp_g,  const float* __restrict__ kp_s,
                 const float* __restrict__ w1,    const float* __restrict__ b1,
                 const float* __restrict__ w2,    const float* __restrict__ b2)
{
    extern __shared__ float sm[];
    float* c1p     = sm;                         // 31744
    float* patch   = sm + SM_C1;                 // 3564 (overlay)
    float* w1t     = patch + NPAT;               // 864
    float* w2t     = sm + SM_C1;                 // 18432 (overlay, after conv1)
    float* partial = sm + SM_C1 + W2T_SZ;        // 1920

    const int p   = blockIdx.x;
    const int set = p >> 10;
    const int m   = p & 1023;
    const int n   = m >> 2;
    const int b   = m & 3;
    const float* img = set ? img_s : img_g;
    const float* kp  = set ? kp_s  : kp_g;

    int sx = (int)floorf(kp[2 * n]     * (float)HW) - SIGMA;
    int sy = (int)floorf(kp[2 * n + 1] * (float)HW) - SIGMA;
    sx = min(max(sx, 0), HW - PATCH);
    sy = min(max(sy, 0), HW - PATCH);

    const int tid = threadIdx.x;

    // ---- stage patch (padded rows) + w1 transposed [ic][ky][oc][kx] ----
    for (int i = tid; i < 3 * PATCH * PATCH; i += 512) {
        int ic = i / (PATCH * PATCH);
        int r  = i % (PATCH * PATCH);
        int y  = r / PATCH, x = r % PATCH;
        patch[ic * PPL + y * PROW + x] =
            img[(((size_t)b * 3 + ic) * HW + (sy + y)) * HW + (sx + x)];
    }
    for (int i = tid; i < W1T_SZ; i += 512) {
        int kx = i % 3;
        int oc = (i / 3) & 31;
        int t  = i / 96;            // ic*3+ky
        int ic = t / 3, ky = t % 3;
        w1t[i] = w1[((oc * 3 + ic) * 3 + ky) * 3 + kx];
    }
    __syncthreads();

    // ---- conv1: 4 oc x 8 x per task; tasks = 8 ocg * 31 y * 4 xt = 992 ----
    for (int t = tid; t < 992; t += 512) {
        const int ocg  = t & 7;
        const int rest = t >> 3;
        const int xt   = rest & 3;
        const int y    = rest >> 2;
        const int x0   = xt * 8;
        const int nv   = (xt == 3) ? 7 : 8;

        float acc[4][8];
        #pragma unroll
        for (int j = 0; j < 4; j++) {
            float bb = b1[4 * ocg + j];
            #pragma unroll
            for (int i = 0; i < 8; i++) acc[j][i] = bb;
        }

        #pragma unroll
        for (int ic = 0; ic < 3; ic++) {
            #pragma unroll
            for (int ky = 0; ky < 3; ky++) {
                float in[12];
                const float4* ip = (const float4*)&patch[ic * PPL + (y + ky) * PROW + x0];
                #pragma unroll
                for (int v = 0; v < 3; v++) {
                    float4 q = ip[v];
                    in[4*v] = q.x; in[4*v+1] = q.y; in[4*v+2] = q.z; in[4*v+3] = q.w;
                }
                float w[12];
                const float4* wp = (const float4*)&w1t[(ic * 3 + ky) * 96 + 12 * ocg];
                #pragma unroll
                for (int v = 0; v < 3; v++) {
                    float4 q = wp[v];
                    w[4*v] = q.x; w[4*v+1] = q.y; w[4*v+2] = q.z; w[4*v+3] = q.w;
                }
                #pragma unroll
                for (int j = 0; j < 4; j++)
                    #pragma unroll
                    for (int lox = 0; lox < 8; lox++)
                        #pragma unroll
                        for (int kx = 0; kx < 3; kx++)
                            acc[j][lox] = fmaf(in[lox + kx], w[j * 3 + kx], acc[j][lox]);
            }
        }

        #pragma unroll
        for (int j = 0; j < 4; j++) {
            float* dst = &c1p[(4 * ocg + j) * C1PL + y * C1ROW + x0];
            if (nv == 8) {
                float4 a = make_float4(fmaxf(acc[j][0],0.f), fmaxf(acc[j][1],0.f),
                                       fmaxf(acc[j][2],0.f), fmaxf(acc[j][3],0.f));
                float4 c = make_float4(fmaxf(acc[j][4],0.f), fmaxf(acc[j][5],0.f),
                                       fmaxf(acc[j][6],0.f), fmaxf(acc[j][7],0.f));
                ((float4*)dst)[0] = a;
                ((float4*)dst)[1] = c;
            } else {
                float4 a = make_float4(fmaxf(acc[j][0],0.f), fmaxf(acc[j][1],0.f),
                                       fmaxf(acc[j][2],0.f), fmaxf(acc[j][3],0.f));
                ((float4*)dst)[0] = a;
                dst[4] = fmaxf(acc[j][4], 0.f);
                dst[5] = fmaxf(acc[j][5], 0.f);
                dst[6] = fmaxf(acc[j][6], 0.f);
            }
        }
    }
    __syncthreads();

    // ---- stage w2 transposed: w2t[ic][ky][oc2][kx] (overwrites patch/w1t) ----
    for (int i = tid; i < W2T_SZ; i += 512) {
        int kx  = i % 3;
        int oc2 = (i / 3) & 63;
        int t   = i / 192;          // ic*3+ky
        int ic  = t / 3, ky = t % 3;
        w2t[i] = w2[((oc2 * C1 + ic) * 3 + ky) * 3 + kx];
    }
    __syncthreads();

    // ---- conv2: 4 oc2 x 8 ox per task; tasks = 16 ocg * 15 oy * 2 xt = 480 ----
    if (tid < 480) {
        const int ocg  = tid & 15;
        const int rest = tid >> 4;
        const int xt   = rest & 1;
        const int oy   = rest >> 1;
        const int x0   = xt * 16;          // input x base (= 2 * ox0)
        const int nv   = xt ? 7 : 8;

        float acc[4][8];
        #pragma unroll
        for (int j = 0; j < 4; j++) {
            float bb = b2[4 * ocg + j];
            #pragma unroll
            for (int i = 0; i < 8; i++) acc[j][i] = bb;
        }

        #pragma unroll 2
        for (int ic = 0; ic < C1; ic++) {
            #pragma unroll
            for (int ky = 0; ky < 3; ky++) {
                float in[20];
                const float4* ip = (const float4*)&c1p[ic * C1PL + (2 * oy + ky) * C1ROW + x0];
                #pragma unroll
                for (int v = 0; v < 5; v++) {
                    float4 q = ip[v];
                    in[4*v] = q.x; in[4*v+1] = q.y; in[4*v+2] = q.z; in[4*v+3] = q.w;
                }
                float w[12];
                const float4* wp = (const float4*)&w2t[(ic * 3 + ky) * 192 + 12 * ocg];
                #pragma unroll
                for (int v = 0; v < 3; v++) {
                    float4 q = wp[v];
                    w[4*v] = q.x; w[4*v+1] = q.y; w[4*v+2] = q.z; w[4*v+3] = q.w;
                }
                #pragma unroll
                for (int j = 0; j < 4; j++)
                    #pragma unroll
                    for (int lox = 0; lox < 8; lox++)
                        #pragma unroll
                        for (int kx = 0; kx < 3; kx++)
                            acc[j][lox] = fmaf(in[2 * lox + kx], w[j * 3 + kx], acc[j][lox]);
            }
        }

        #pragma unroll
        for (int j = 0; j < 4; j++) {
            float s = 0.0f;
            #pragma unroll
            for (int lox = 0; lox < 8; lox++)
                if (lox < nv) s += fmaxf(acc[j][lox], 0.0f);
            partial[(4 * ocg + j) * 30 + oy * 2 + xt] = s;
        }
    }
    __syncthreads();

    // ---- GAP: thread oc2 sums its 30 partials (fixed order, deterministic) ----
    if (tid < C2) {
        float s = 0.0f;
        #pragma unroll
        for (int i = 0; i < 30; i++) s += partial[tid * 30 + i];
        g_h[((size_t)set * NPATCH + m) * C2 + tid] = s * (1.0f / 225.0f);
    }
}

// ---------------------------------------------------------------------------
// Kernel B: per-pair projected squared diff. y = wl @ (hg - hs); sum y^2.
// (bl cancels exactly in fg - fs.)
// ---------------------------------------------------------------------------
__global__ void __launch_bounds__(128)
pair_kernel(const float* __restrict__ wl)
{
    __shared__ float d[C2];
    __shared__ float red[OUTF];
    const int pair = blockIdx.x;
    const int tid  = threadIdx.x;

    const float* hg = &g_h[(size_t)pair * C2];
    const float* hs = &g_h[((size_t)NPATCH + pair) * C2];
    if (tid < C2) d[tid] = hg[tid] - hs[tid];
    __syncthreads();

    float y = 0.0f;
    const float* wr = &wl[tid * C2];
    #pragma unroll
    for (int i = 0; i < C2; i++) y += wr[i] * d[i];
    red[tid] = y * y;
    __syncthreads();
    #pragma unroll
    for (int s = OUTF / 2; s > 0; s >>= 1) {
        if (tid < s) red[tid] += red[tid + s];
        __syncthreads();
    }
    if (tid == 0) g_pairsum[pair] = red[0];
}

// ---------------------------------------------------------------------------
// Kernel C: final deterministic reduction + mean.
// ---------------------------------------------------------------------------
__global__ void __launch_bounds__(256)
reduce_kernel(float* __restrict__ out)
{
    __shared__ float red[256];
    const int tid = threadIdx.x;
    float s = 0.0f;
    for (int i = tid; i < NPATCH; i += 256) s += g_pairsum[i];
    red[tid] = s;
    __syncthreads();
    #pragma unroll
    for (int st = 128; st > 0; st >>= 1) {
        if (tid < st) red[tid] += red[tid + st];
        __syncthreads();
    }
    if (tid == 0)
        out[0] = red[0] / (float)((size_t)NPATCH * OUTF);
}

// ---------------------------------------------------------------------------
extern "C" void kernel_launch(void* const* d_in, const int* in_sizes, int n_in,
                              void* d_out, int out_size)
{
    const float* img_g = (const float*)d_in[0];
    const float* img_s = (const float*)d_in[1];
    const float* kp_g  = (const float*)d_in[2];
    const float* kp_s  = (const float*)d_in[3];
    const float* w1    = (const float*)d_in[4];
    const float* b1    = (const float*)d_in[5];
    const float* w2    = (const float*)d_in[6];
    const float* b2    = (const float*)d_in[7];
    const float* wl    = (const float*)d_in[8];
    // d_in[9] = bl (cancels), d_in[10] = num_samples (fixed)

    const int smem_bytes = SM_TOTAL * (int)sizeof(float);
    cudaFuncSetAttribute(patch_cnn_kernel,
                         cudaFuncAttributeMaxDynamicSharedMemorySize, smem_bytes);

    patch_cnn_kernel<<<2 * NPATCH, 512, smem_bytes>>>(img_g, img_s, kp_g, kp_s,
                                                      w1, b1, w2, b2);
    pair_kernel<<<NPATCH, 128>>>(wl);
    reduce_kernel<<<1, 256>>>((float*)d_out);
}

// round 6
// speedup vs baseline: 6.2003x; 2.6015x over previous
#include <cuda_runtime.h>
#include <cuda_bf16.h>
#include <cstdint>

// Fixed problem shapes
#define SIGMA   16
#define PATCH   33
#define HW      256
#define NPATCH  1024
#define C1      32
#define C1H     31
#define C2      64
#define C2H     15
#define OUTF    128

// conv1 fp32 patch staging (padded rows)
#define PROW    36
#define PPL     (PATCH * PROW)          // 1188 floats / channel

// smem byte layout
//  quads: 4 quadrants x 256 pixel-rows x 80B (32 ic bf16 = 64B data + 16B pad)
#define QUAD_OFF   0
#define QROW       80
#define QUAD_BYTES (1024 * QROW)        // 81920
//  w2s:  9 taps x 64 oc rows x 80B (32 ic bf16)
#define W2S_OFF    81920                // + 46080 -> 128000
#define PATCH_OFF  128000               // 3*1188*4 = 14256
#define W1T_OFF    142336               // 864*4   = 3456
#define B2S_OFF    145792               // 64*4
#define PART_OFF   146048               // 16*64*4 = 4096
#define SMEM_BYTES 150528

__device__ float g_h[2 * NPATCH * C2];
__device__ float g_pairsum[NPATCH];

__device__ __forceinline__ uint32_t smem_u32(const void* p) {
    uint32_t a;
    asm("{ .reg .u64 t; cvta.to.shared.u64 t, %1; cvt.u32.u64 %0, t; }" : "=r"(a) : "l"(p));
    return a;
}

__device__ __forceinline__ void ldsm_x4(uint32_t addr, uint32_t& r0, uint32_t& r1,
                                        uint32_t& r2, uint32_t& r3) {
    asm volatile("ldmatrix.sync.aligned.m8n8.x4.shared.b16 {%0,%1,%2,%3}, [%4];"
                 : "=r"(r0), "=r"(r1), "=r"(r2), "=r"(r3) : "r"(addr));
}

__device__ __forceinline__ void mma16816(float* d, uint32_t a0, uint32_t a1,
                                         uint32_t a2, uint32_t a3,
                                         uint32_t b0, uint32_t b1) {
    asm volatile("mma.sync.aligned.m16n8k16.row.col.f32.bf16.bf16.f32 "
                 "{%0,%1,%2,%3}, {%4,%5,%6,%7}, {%8,%9}, {%0,%1,%2,%3};"
                 : "+f"(d[0]), "+f"(d[1]), "+f"(d[2]), "+f"(d[3])
                 : "r"(a0), "r"(a1), "r"(a2), "r"(a3), "r"(b0), "r"(b1));
}

// ---------------------------------------------------------------------------
// Kernel A: per-patch CNN up to GAP. One block/patch (2048 x 512).
// conv1: FFMA register-tiled -> bf16 quadrants. conv2: mma.sync bf16 HMMA.
// ---------------------------------------------------------------------------
__global__ void __launch_bounds__(512, 1)
patch_cnn_kernel(const float* __restrict__ img_g, const float* __restrict__ img_s,
                 const float* __restrict__ kp_g,  const float* __restrict__ kp_s,
                 const float* __restrict__ w1,    const float* __restrict__ b1,
                 const float* __restrict__ w2,    const float* __restrict__ b2)
{
    extern __shared__ char smc[];
    float* patch = (float*)(smc + PATCH_OFF);
    float* w1t   = (float*)(smc + W1T_OFF);
    float* b2s   = (float*)(smc + B2S_OFF);
    float* part  = (float*)(smc + PART_OFF);
    const uint32_t smb = smem_u32(smc);

    const int p   = blockIdx.x;
    const int set = p >> 10;
    const int m   = p & 1023;
    const int n   = m >> 2;
    const int b   = m & 3;
    const float* img = set ? img_s : img_g;
    const float* kp  = set ? kp_s  : kp_g;

    int sx = (int)floorf(kp[2 * n]     * (float)HW) - SIGMA;
    int sy = (int)floorf(kp[2 * n + 1] * (float)HW) - SIGMA;
    sx = min(max(sx, 0), HW - PATCH);
    sy = min(max(sy, 0), HW - PATCH);

    const int tid = threadIdx.x;
    const int wid = tid >> 5;
    const int lid = tid & 31;

    // ---- pre-pass: zero quads; stage patch, w1t, w2 (bf16), b2 ----
    for (int i = tid; i < QUAD_BYTES / 16; i += 512)
        *(float4*)(smc + QUAD_OFF + i * 16) = make_float4(0.f, 0.f, 0.f, 0.f);
    for (int i = tid; i < 3 * PATCH * PATCH; i += 512) {
        int ic = i / (PATCH * PATCH);
        int r  = i % (PATCH * PATCH);
        int y  = r / PATCH, x = r % PATCH;
        patch[ic * PPL + y * PROW + x] =
            img[(((size_t)b * 3 + ic) * HW + (sy + y)) * HW + (sx + x)];
    }
    for (int i = tid; i < C1 * 27; i += 512) {
        int kx = i % 3;
        int oc = (i / 3) & 31;
        int t  = i / 96;
        int ic = t / 3, ky = t % 3;
        w1t[i] = w1[((oc * 3 + ic) * 3 + ky) * 3 + kx];
    }
    // w2 -> w2s[tap][oc][ic] bf16 (rows 80B)
    for (int i = tid; i < 9 * 64 * 16; i += 512) {
        int icp = i & 15;              // ic pair
        int oc  = (i >> 4) & 63;
        int tap = i >> 10;
        int ky = tap / 3, kx = tap - 3 * ky;
        const float* ws = w2 + ((size_t)(oc * C1 + 2 * icp) * 3 + ky) * 3 + kx;
        __nv_bfloat162 v = __floats2bfloat162_rn(ws[0], ws[9]);
        *(__nv_bfloat162*)(smc + W2S_OFF + (tap * 64 + oc) * QROW + icp * 4) = v;
    }
    if (tid < C2) b2s[tid] = b2[tid];
    __syncthreads();

    // ---- conv1: 4 oc x 8 x per task; 992 tasks; bf16 quadrant output ----
    for (int t = tid; t < 992; t += 512) {
        const int ocg  = t & 7;
        const int rest = t >> 3;
        const int xt   = rest & 3;
        const int y    = rest >> 2;
        const int x0   = xt * 8;
        const int nv   = (xt == 3) ? 7 : 8;

        float acc[4][8];
        #pragma unroll
        for (int j = 0; j < 4; j++) {
            float bb = b1[4 * ocg + j];
            #pragma unroll
            for (int i = 0; i < 8; i++) acc[j][i] = bb;
        }

        #pragma unroll
        for (int ic = 0; ic < 3; ic++) {
            #pragma unroll
            for (int ky = 0; ky < 3; ky++) {
                float in[12];
                const float4* ip = (const float4*)&patch[ic * PPL + (y + ky) * PROW + x0];
                #pragma unroll
                for (int v = 0; v < 3; v++) {
                    float4 q = ip[v];
                    in[4*v] = q.x; in[4*v+1] = q.y; in[4*v+2] = q.z; in[4*v+3] = q.w;
                }
                float w[12];
                const float4* wp = (const float4*)&w1t[(ic * 3 + ky) * 96 + 12 * ocg];
                #pragma unroll
                for (int v = 0; v < 3; v++) {
                    float4 q = wp[v];
                    w[4*v] = q.x; w[4*v+1] = q.y; w[4*v+2] = q.z; w[4*v+3] = q.w;
                }
                #pragma unroll
                for (int j = 0; j < 4; j++)
                    #pragma unroll
                    for (int lox = 0; lox < 8; lox++)
                        #pragma unroll
                        for (int kx = 0; kx < 3; kx++)
                            acc[j][lox] = fmaf(in[lox + kx], w[j * 3 + kx], acc[j][lox]);
            }
        }

        #pragma unroll
        for (int i = 0; i < 8; i++) {
            if (i < nv) {
                int x    = x0 + i;
                int quad = ((y & 1) << 1) | (x & 1);
                int row  = quad * 256 + ((y >> 1) << 4) + (x >> 1);
                __nv_bfloat162 lo = __floats2bfloat162_rn(fmaxf(acc[0][i], 0.f),
                                                          fmaxf(acc[1][i], 0.f));
                __nv_bfloat162 hi = __floats2bfloat162_rn(fmaxf(acc[2][i], 0.f),
                                                          fmaxf(acc[3][i], 0.f));
                uint2 v;
                v.x = *(uint32_t*)&lo;
                v.y = *(uint32_t*)&hi;
                *(uint2*)(smc + QUAD_OFF + row * QROW + ocg * 8) = v;
            }
        }
    }
    __syncthreads();

    // ---- conv2 via mma.sync: warp w owns output row oy=w (16 pixels x 64 oc) ----
    float acc[8][4];
    #pragma unroll
    for (int i = 0; i < 8; i++)
        #pragma unroll
        for (int j = 0; j < 4; j++) acc[i][j] = 0.0f;

    const int w = wid;                       // 0..15 = oy
    const uint32_t a_row = (uint32_t)(lid & 15);
    const uint32_t a_kh  = (uint32_t)(lid >> 4);            // +16B for k8..15
    const uint32_t b_row = (uint32_t)((lid & 7) + ((lid >> 4) << 3));
    const uint32_t b_kh  = (uint32_t)((lid >> 3) & 1);

    #pragma unroll
    for (int tap = 0; tap < 9; tap++) {
        const int ky = tap / 3, kx = tap - 3 * ky;
        const int quad = ((ky & 1) << 1) | (kx & 1);
        const int d    = ((ky >> 1) << 4) + (kx >> 1);
        const uint32_t a_base = smb + QUAD_OFF +
            (uint32_t)(quad * 256 + w * 16 + d + a_row) * QROW + a_kh * 16;
        const uint32_t b_base = smb + W2S_OFF +
            (uint32_t)(tap * 64 + b_row) * QROW + b_kh * 16;

        #pragma unroll
        for (int ks = 0; ks < 2; ks++) {
            uint32_t a0, a1, a2, a3;
            ldsm_x4(a_base + ks * 32, a0, a1, a2, a3);
            #pragma unroll
            for (int ntp = 0; ntp < 4; ntp++) {
                uint32_t b0, b1, b2r, b3;
                ldsm_x4(b_base + (uint32_t)(ntp * 16) * QROW + ks * 32, b0, b1, b2r, b3);
                mma16816(acc[2 * ntp],     a0, a1, a2, a3, b0,  b1);
                mma16816(acc[2 * ntp + 1], a0, a1, a2, a3, b2r, b3);
            }
        }
    }

    // ---- epilogue: relu(D + b2), mask invalid pixels (ox==15 or oy==15), reduce ----
    {
        const bool w_ok  = (w < C2H);
        const bool hi_ok = ((lid >> 2) != 7);   // rit+8 == 15 invalid
        #pragma unroll
        for (int nt = 0; nt < 8; nt++) {
            int c0 = nt * 8 + 2 * (lid & 3);
            float bb0 = b2s[c0], bb1 = b2s[c0 + 1];
            float sA = 0.0f, sB = 0.0f;
            if (w_ok) {
                sA = fmaxf(acc[nt][0] + bb0, 0.0f);
                sB = fmaxf(acc[nt][1] + bb1, 0.0f);
                if (hi_ok) {
                    sA += fmaxf(acc[nt][2] + bb0, 0.0f);
                    sB += fmaxf(acc[nt][3] + bb1, 0.0f);
                }
            }
            #pragma unroll
            for (int msk = 4; msk <= 16; msk <<= 1) {
                sA += __shfl_xor_sync(0xffffffffu, sA, msk);
                sB += __shfl_xor_sync(0xffffffffu, sB, msk);
            }
            if (lid < 4) {
                part[w * 64 + c0]     = sA;
                part[w * 64 + c0 + 1] = sB;
            }
        }
    }
    __syncthreads();

    if (tid < C2) {
        float s = 0.0f;
        #pragma unroll
        for (int ww = 0; ww < 16; ww++) s += part[ww * 64 + tid];
        g_h[((size_t)set * NPATCH + m) * C2 + tid] = s * (1.0f / 225.0f);
    }
}

// ---------------------------------------------------------------------------
// Kernel B: per-pair projected squared diff. y = wl @ (hg - hs); sum y^2.
// (bl cancels exactly in fg - fs.)
// ---------------------------------------------------------------------------
__global__ void __launch_bounds__(128)
pair_kernel(const float* __restrict__ wl)
{
    __shared__ float d[C2];
    __shared__ float red[OUTF];
    const int pair = blockIdx.x;
    const int tid  = threadIdx.x;

    const float* hg = &g_h[(size_t)pair * C2];
    const float* hs = &g_h[((size_t)NPATCH + pair) * C2];
    if (tid < C2) d[tid] = hg[tid] - hs[tid];
    __syncthreads();

    float y = 0.0f;
    const float* wr = &wl[tid * C2];
    #pragma unroll
    for (int i = 0; i < C2; i++) y += wr[i] * d[i];
    red[tid] = y * y;
    __syncthreads();
    #pragma unroll
    for (int s = OUTF / 2; s > 0; s >>= 1) {
        if (tid < s) red[tid] += red[tid + s];
        __syncthreads();
    }
    if (tid == 0) g_pairsum[pair] = red[0];
}

// ---------------------------------------------------------------------------
// Kernel C: final deterministic reduction + mean.
// ---------------------------------------------------------------------------
__global__ void __launch_bounds__(256)
reduce_kernel(float* __restrict__ out)
{
    __shared__ float red[256];
    const int tid = threadIdx.x;
    float s = 0.0f;
    for (int i = tid; i < NPATCH; i += 256) s += g_pairsum[i];
    red[tid] = s;
    __syncthreads();
    #pragma unroll
    for (int st = 128; st > 0; st >>= 1) {
        if (tid < st) red[tid] += red[tid + st];
        __syncthreads();
    }
    if (tid == 0)
        out[0] = red[0] / (float)((size_t)NPATCH * OUTF);
}

// ---------------------------------------------------------------------------
extern "C" void kernel_launch(void* const* d_in, const int* in_sizes, int n_in,
                              void* d_out, int out_size)
{
    const float* img_g = (const float*)d_in[0];
    const float* img_s = (const float*)d_in[1];
    const float* kp_g  = (const float*)d_in[2];
    const float* kp_s  = (const float*)d_in[3];
    const float* w1    = (const float*)d_in[4];
    const float* b1    = (const float*)d_in[5];
    const float* w2    = (const float*)d_in[6];
    const float* b2    = (const float*)d_in[7];
    const float* wl    = (const float*)d_in[8];
    // d_in[9] = bl (cancels), d_in[10] = num_samples (fixed)

    cudaFuncSetAttribute(patch_cnn_kernel,
                         cudaFuncAttributeMaxDynamicSharedMemorySize, SMEM_BYTES);

    patch_cnn_kernel<<<2 * NPATCH, 512, SMEM_BYTES>>>(img_g, img_s, kp_g, kp_s,
                                                      w1, b1, w2, b2);
    pair_kernel<<<NPATCH, 128>>>(wl);
    reduce_kernel<<<1, 256>>>((float*)d_out);
}

// round 8
// speedup vs baseline: 7.2762x; 1.1735x over previous
#include <cuda_runtime.h>
#include <cuda_bf16.h>
#include <cstdint>

// Fixed problem shapes
#define SIGMA   16
#define PATCH   33
#define HW      256
#define NPATCH  1024
#define C1      32
#define C1H     31
#define C2      64
#define C2H     15
#define OUTF    128

// conv1 fp32 patch staging (padded rows)
#define PROW    36
#define PPL     (PATCH * PROW)          // 1188 floats / channel

// smem byte layout
//  buf0: im2col A (1024 rows x 80B) then reused as conv1-output quadrants
#define BUF0_OFF   0
#define QROW       80
#define BUF0_BYTES (1024 * QROW)        // 81920
#define W2S_OFF    81920                // 9 taps x 64 oc x 80B = 46080
#define PATCH_OFF  128000               // 3*1188*4 = 14256 (pad 14336)
#define W1B_OFF    142336               // 32 oc x 80B = 2560
#define B1S_OFF    144896               // 32*4
#define B2S_OFF    145024               // 64*4
#define PART_OFF   145280               // 16*64*4 = 4096
#define SMEM_BYTES 149504

__device__ float g_h[2 * NPATCH * C2];
__device__ float g_pairsum[NPATCH];

__device__ __forceinline__ uint32_t smem_u32(const void* p) {
    uint32_t a;
    asm("{ .reg .u64 t; cvta.to.shared.u64 t, %1; cvt.u32.u64 %0, t; }" : "=r"(a) : "l"(p));
    return a;
}

__device__ __forceinline__ void ldsm_x4(uint32_t addr, uint32_t& r0, uint32_t& r1,
                                        uint32_t& r2, uint32_t& r3) {
    asm volatile("ldmatrix.sync.aligned.m8n8.x4.shared.b16 {%0,%1,%2,%3}, [%4];"
                 : "=r"(r0), "=r"(r1), "=r"(r2), "=r"(r3) : "r"(addr));
}

__device__ __forceinline__ void mma16816(float* d, uint32_t a0, uint32_t a1,
                                         uint32_t a2, uint32_t a3,
                                         uint32_t b0, uint32_t b1) {
    asm volatile("mma.sync.aligned.m16n8k16.row.col.f32.bf16.bf16.f32 "
                 "{%0,%1,%2,%3}, {%4,%5,%6,%7}, {%8,%9}, {%0,%1,%2,%3};"
                 : "+f"(d[0]), "+f"(d[1]), "+f"(d[2]), "+f"(d[3])
                 : "r"(a0), "r"(a1), "r"(a2), "r"(a3), "r"(b0), "r"(b1));
}

__device__ __forceinline__ uint32_t bfpack(float lo, float hi) {
    __nv_bfloat162 v = __floats2bfloat162_rn(lo, hi);
    return *(uint32_t*)&v;
}

// quadrant smem row byte-offset for conv1-output pixel m = y*31+x
__device__ __forceinline__ uint32_t quad_row_off(int m) {
    int y = m / 31;
    int x = m - 31 * y;
    int row = ((((y & 1) << 1) | (x & 1)) << 8) + ((y >> 1) << 4) + (x >> 1);
    return (uint32_t)row * QROW;
}

// ---------------------------------------------------------------------------
// Kernel A: per-patch CNN up to GAP. One block/patch (2048 x 512).
// conv1: im2col + mma.sync bf16.  conv2: 9 shifted GEMMs, mma.sync bf16.
// ---------------------------------------------------------------------------
__global__ void __launch_bounds__(512, 1)
patch_cnn_kernel(const float* __restrict__ img_g, const float* __restrict__ img_s,
                 const float* __restrict__ kp_g,  const float* __restrict__ kp_s,
                 const float* __restrict__ w1,    const float* __restrict__ b1,
                 const float* __restrict__ w2,    const float* __restrict__ b2)
{
    extern __shared__ char smc[];
    float* patch = (float*)(smc + PATCH_OFF);
    float* b1s   = (float*)(smc + B1S_OFF);
    float* b2s   = (float*)(smc + B2S_OFF);
    float* part  = (float*)(smc + PART_OFF);
    const uint32_t smb = smem_u32(smc);

    const int p   = blockIdx.x;
    const int set = p >> 10;
    const int m   = p & 1023;
    const int n   = m >> 2;
    const int b   = m & 3;
    const float* img = set ? img_s : img_g;
    const float* kp  = set ? kp_s  : kp_g;

    int sx = (int)floorf(kp[2 * n]     * (float)HW) - SIGMA;
    int sy = (int)floorf(kp[2 * n + 1] * (float)HW) - SIGMA;
    sx = min(max(sx, 0), HW - PATCH);
    sy = min(max(sy, 0), HW - PATCH);

    const int tid = threadIdx.x;
    const int wid = tid >> 5;
    const int lid = tid & 31;

    // ---- stage: patch fp32, w1b bf16 (32 rows x 80B), w2s bf16, biases ----
    for (int i = tid; i < 3 * PATCH * PATCH; i += 512) {
        int ic = i / (PATCH * PATCH);
        int r  = i % (PATCH * PATCH);
        int y  = r / PATCH, x = r % PATCH;
        patch[ic * PPL + y * PROW + x] =
            img[(((size_t)b * 3 + ic) * HW + (sy + y)) * HW + (sx + x)];
    }
    {   // w1b[oc][k], k = ic*9+ky*3+kx == linear OIHW tail -> contiguous
        int oc = tid >> 4, pr = tid & 15;           // 512 = 32*16 exactly
        float lo = (2 * pr     < 27) ? w1[oc * 27 + 2 * pr]     : 0.f;
        float hi = (2 * pr + 1 < 27) ? w1[oc * 27 + 2 * pr + 1] : 0.f;
        *(uint32_t*)(smc + W1B_OFF + oc * QROW + pr * 4) = bfpack(lo, hi);
    }
    for (int i = tid; i < 9 * 64 * 16; i += 512) {   // w2s[tap][oc][ic]
        int icp = i & 15;
        int oc  = (i >> 4) & 63;
        int tap = i >> 10;
        int ky = tap / 3, kx = tap - 3 * ky;
        const float* ws = w2 + ((size_t)(oc * C1 + 2 * icp) * 3 + ky) * 3 + kx;
        *(uint32_t*)(smc + W2S_OFF + (tap * 64 + oc) * QROW + icp * 4) =
            bfpack(ws[0], ws[9]);
    }
    if (tid < C1) b1s[tid] = b1[tid];
    else if (tid < C1 + C2) b2s[tid - C1] = b2[tid - C1];
    __syncthreads();

    // ---- im2col: A[m=y*31+x][k=ic*9+ky*3+kx] bf16, rows 80B ----
    for (int mm = tid; mm < 961; mm += 512) {
        int y = mm / 31, x = mm - 31 * y;
        float v[27];
        #pragma unroll
        for (int ic = 0; ic < 3; ic++)
            #pragma unroll
            for (int ky = 0; ky < 3; ky++) {
                const float* rp = &patch[ic * PPL + (y + ky) * PROW + x];
                v[ic * 9 + ky * 3 + 0] = rp[0];
                v[ic * 9 + ky * 3 + 1] = rp[1];
                v[ic * 9 + ky * 3 + 2] = rp[2];
            }
        uint32_t r[16];
        #pragma unroll
        for (int i = 0; i < 13; i++) r[i] = bfpack(v[2 * i], v[2 * i + 1]);
        r[13] = bfpack(v[26], 0.f);
        r[14] = 0u; r[15] = 0u;
        uint4* dst = (uint4*)(smc + BUF0_OFF + mm * QROW);
        dst[0] = make_uint4(r[0], r[1], r[2], r[3]);
        dst[1] = make_uint4(r[4], r[5], r[6], r[7]);
        dst[2] = make_uint4(r[8], r[9], r[10], r[11]);
        dst[3] = make_uint4(r[12], r[13], r[14], r[15]);
    }
    __syncthreads();

    // ---- conv1 GEMM: M=1024 (961 valid), N=32, K=32; warp w -> rows 64w..64w+63
    const uint32_t a_row = (uint32_t)(lid & 15);
    const uint32_t a_kh  = (uint32_t)(lid >> 4);
    const uint32_t b_row = (uint32_t)((lid & 7) + ((lid >> 4) << 3));
    const uint32_t b_kh  = (uint32_t)((lid >> 3) & 1);

    uint32_t qv[4][4][2];        // [tile][n8 j][row-half]
    uint32_t qoff[4][2];
    bool     qok[4][2];
    {
        uint32_t bw[2][2][4];    // [ks][n16 g]
        #pragma unroll
        for (int ks = 0; ks < 2; ks++)
            #pragma unroll
            for (int g = 0; g < 2; g++)
                ldsm_x4(smb + W1B_OFF + (g * 16 + b_row) * QROW + b_kh * 16 + ks * 32,
                        bw[ks][g][0], bw[ks][g][1], bw[ks][g][2], bw[ks][g][3]);

        float b1c0[4], b1c1[4];
        #pragma unroll
        for (int j = 0; j < 4; j++) {
            int c0 = j * 8 + 2 * (lid & 3);
            b1c0[j] = b1s[c0];
            b1c1[j] = b1s[c0 + 1];
        }

        #pragma unroll
        for (int t = 0; t < 4; t++) {
            const int r0 = wid * 64 + t * 16;
            uint32_t a[2][4];
            #pragma unroll
            for (int ks = 0; ks < 2; ks++)
                ldsm_x4(smb + BUF0_OFF + (r0 + a_row) * QROW + a_kh * 16 + ks * 32,
                        a[ks][0], a[ks][1], a[ks][2], a[ks][3]);
            float d[4][4];
            #pragma unroll
            for (int j = 0; j < 4; j++)
                #pragma unroll
                for (int q = 0; q < 4; q++) d[j][q] = 0.0f;
            #pragma unroll
            for (int ks = 0; ks < 2; ks++)
                #pragma unroll
                for (int g = 0; g < 2; g++) {
                    mma16816(d[2 * g],     a[ks][0], a[ks][1], a[ks][2], a[ks][3],
                             bw[ks][g][0], bw[ks][g][1]);
                    mma16816(d[2 * g + 1], a[ks][0], a[ks][1], a[ks][2], a[ks][3],
                             bw[ks][g][2], bw[ks][g][3]);
                }
            const int m_lo = r0 + (lid >> 2);
            const int m_hi = m_lo + 8;
            qok[t][0]  = (m_lo < 961);
            qok[t][1]  = (m_hi < 961);
            qoff[t][0] = quad_row_off(m_lo);
            qoff[t][1] = quad_row_off(m_hi);
            #pragma unroll
            for (int j = 0; j < 4; j++) {
                qv[t][j][0] = bfpack(fmaxf(d[j][0] + b1c0[j], 0.f),
                                     fmaxf(d[j][1] + b1c1[j], 0.f));
                qv[t][j][1] = bfpack(fmaxf(d[j][2] + b1c0[j], 0.f),
                                     fmaxf(d[j][3] + b1c1[j], 0.f));
            }
        }
    }
    __syncthreads();   // all A reads done -> safe to overwrite buf0 as quadrants

    // ---- scatter conv1 output into quadrant layout (conflict-free) ----
    {
        const uint32_t cb = (uint32_t)(2 * (lid & 3)) * 2;   // byte offset of col pair
        #pragma unroll
        for (int t = 0; t < 4; t++)
            #pragma unroll
            for (int h = 0; h < 2; h++)
                if (qok[t][h]) {
                    char* base = smc + BUF0_OFF + qoff[t][h] + cb;
                    #pragma unroll
                    for (int j = 0; j < 4; j++)
                        *(uint32_t*)(base + j * 16) = qv[t][j][h];
                }
    }
    __syncthreads();

    // ---- conv2 via mma.sync: warp w = oy; 9 shifted taps ----
    float acc[8][4];
    #pragma unroll
    for (int i = 0; i < 8; i++)
        #pragma unroll
        for (int j = 0; j < 4; j++) acc[i][j] = 0.0f;

    const int w = wid;
    #pragma unroll
    for (int tap = 0; tap < 9; tap++) {
        const int ky = tap / 3, kx = tap - 3 * ky;
        const int quad = ((ky & 1) << 1) | (kx & 1);
        const int d0   = ((ky >> 1) << 4) + (kx >> 1);
        const uint32_t a_base = smb + BUF0_OFF +
            (uint32_t)(quad * 256 + w * 16 + d0 + a_row) * QROW + a_kh * 16;
        const uint32_t b_base = smb + W2S_OFF +
            (uint32_t)(tap * 64 + b_row) * QROW + b_kh * 16;

        #pragma unroll
        for (int ks = 0; ks < 2; ks++) {
            uint32_t a0, a1, a2, a3;
            ldsm_x4(a_base + ks * 32, a0, a1, a2, a3);
            #pragma unroll
            for (int ntp = 0; ntp < 4; ntp++) {
                uint32_t b0, b1r, b2r, b3;
                ldsm_x4(b_base + (uint32_t)(ntp * 16) * QROW + ks * 32, b0, b1r, b2r, b3);
                mma16816(acc[2 * ntp],     a0, a1, a2, a3, b0,  b1r);
                mma16816(acc[2 * ntp + 1], a0, a1, a2, a3, b2r, b3);
            }
        }
    }

    // ---- epilogue: relu(D + b2), mask (ox==15 | oy==15), reduce ----
    {
        const bool w_ok  = (w < C2H);
        const bool hi_ok = ((lid >> 2) != 7);
        #pragma unroll
        for (int nt = 0; nt < 8; nt++) {
            int c0 = nt * 8 + 2 * (lid & 3);
            float bb0 = b2s[c0], bb1 = b2s[c0 + 1];
            float sA = 0.0f, sB = 0.0f;
            if (w_ok) {
                sA = fmaxf(acc[nt][0] + bb0, 0.0f);
                sB = fmaxf(acc[nt][1] + bb1, 0.0f);
                if (hi_ok) {
                    sA += fmaxf(acc[nt][2] + bb0, 0.0f);
                    sB += fmaxf(acc[nt][3] + bb1, 0.0f);
                }
            }
            #pragma unroll
            for (int msk = 4; msk <= 16; msk <<= 1) {
                sA += __shfl_xor_sync(0xffffffffu, sA, msk);
                sB += __shfl_xor_sync(0xffffffffu, sB, msk);
            }
            if (lid < 4) {
                part[w * 64 + c0]     = sA;
                part[w * 64 + c0 + 1] = sB;
            }
        }
    }
    __syncthreads();

    if (tid < C2) {
        float s = 0.0f;
        #pragma unroll
        for (int ww = 0; ww < 16; ww++) s += part[ww * 64 + tid];
        g_h[((size_t)set * NPATCH + m) * C2 + tid] = s * (1.0f / 225.0f);
    }
}

// ---------------------------------------------------------------------------
// Kernel B: per-pair projected squared diff. y = wl @ (hg - hs); sum y^2.
// ---------------------------------------------------------------------------
__global__ void __launch_bounds__(128)
pair_kernel(const float* __restrict__ wl)
{
    __shared__ float d[C2];
    __shared__ float red[OUTF];
    const int pair = blockIdx.x;
    const int tid  = threadIdx.x;

    const float* hg = &g_h[(size_t)pair * C2];
    const float* hs = &g_h[((size_t)NPATCH + pair) * C2];
    if (tid < C2) d[tid] = hg[tid] - hs[tid];
    __syncthreads();

    float y = 0.0f;
    const float* wr = &wl[tid * C2];
    #pragma unroll
    for (int i = 0; i < C2; i++) y += wr[i] * d[i];
    red[tid] = y * y;
    __syncthreads();
    #pragma unroll
    for (int s = OUTF / 2; s > 0; s >>= 1) {
        if (tid < s) red[tid] += red[tid + s];
        __syncthreads();
    }
    if (tid == 0) g_pairsum[pair] = red[0];
}

// ---------------------------------------------------------------------------
// Kernel C: final deterministic reduction + mean.
// ---------------------------------------------------------------------------
__global__ void __launch_bounds__(256)
reduce_kernel(float* __restrict__ out)
{
    __shared__ float red[256];
    const int tid = threadIdx.x;
    float s = 0.0f;
    for (int i = tid; i < NPATCH; i += 256) s += g_pairsum[i];
    red[tid] = s;
    __syncthreads();
    #pragma unroll
    for (int st = 128; st > 0; st >>= 1) {
        if (tid < st) red[tid] += red[tid + st];
        __syncthreads();
    }
    if (tid == 0)
        out[0] = red[0] / (float)((size_t)NPATCH * OUTF);
}

// ---------------------------------------------------------------------------
extern "C" void kernel_launch(void* const* d_in, const int* in_sizes, int n_in,
                              void* d_out, int out_size)
{
    const float* img_g = (const float*)d_in[0];
    const float* img_s = (const float*)d_in[1];
    const float* kp_g  = (const float*)d_in[2];
    const float* kp_s  = (const float*)d_in[3];
    const float* w1    = (const float*)d_in[4];
    const float* b1    = (const float*)d_in[5];
    const float* w2    = (const float*)d_in[6];
    const float* b2    = (const float*)d_in[7];
    const float* wl    = (const float*)d_in[8];
    // d_in[9] = bl (cancels), d_in[10] = num_samples (fixed)

    cudaFuncSetAttribute(patch_cnn_kernel,
                         cudaFuncAttributeMaxDynamicSharedMemorySize, SMEM_BYTES);

    patch_cnn_kernel<<<2 * NPATCH, 512, SMEM_BYTES>>>(img_g, img_s, kp_g, kp_s,
                                                      w1, b1, w2, b2);
    pair_kernel<<<NPATCH, 128>>>(wl);
    reduce_kernel<<<1, 256>>>((float*)d_out);
}

// round 9
// speedup vs baseline: 8.9288x; 1.2271x over previous
#include <cuda_runtime.h>
#include <cuda_bf16.h>
#include <cstdint>

// Fixed problem shapes
#define SIGMA   16
#define PATCH   33
#define HW      256
#define NPATCH  1024
#define C1      32
#define C1H     31
#define C2      64
#define C2H     15
#define OUTF    128

// conv1 fp32 patch staging (padded rows)
#define PROW    36
#define PPL     (PATCH * PROW)          // 1188 floats / channel

// smem byte layout
#define BUF0_OFF   0
#define QROW       80
#define BUF0_BYTES (1024 * QROW)        // 81920
#define W2S_OFF    81920                // 9*64 rows x 80B = 46080
#define PATCH_OFF  128000               // 3*1188*4 = 14256 (pad 14336)
#define W1B_OFF    142336               // 32 rows x 80B = 2560
#define B1S_OFF    144896               // 32*4
#define B2S_OFF    145024               // 64*4
#define PART_OFF   145280               // 16*64*4 = 4096
#define SMEM_BYTES 149504

__device__ float g_h[2 * NPATCH * C2];
__device__ float g_pairsum[NPATCH];
// pre-converted weight images (bf16, 80B rows) — written by prep_kernel
__device__ uint4 g_w2s4[2880];          // 46080 B
__device__ uint4 g_w1b4[160];           // 2560 B

__device__ __forceinline__ uint32_t smem_u32(const void* p) {
    uint32_t a;
    asm("{ .reg .u64 t; cvta.to.shared.u64 t, %1; cvt.u32.u64 %0, t; }" : "=r"(a) : "l"(p));
    return a;
}

__device__ __forceinline__ void ldsm_x4(uint32_t addr, uint32_t& r0, uint32_t& r1,
                                        uint32_t& r2, uint32_t& r3) {
    asm volatile("ldmatrix.sync.aligned.m8n8.x4.shared.b16 {%0,%1,%2,%3}, [%4];"
                 : "=r"(r0), "=r"(r1), "=r"(r2), "=r"(r3) : "r"(addr));
}

__device__ __forceinline__ void mma16816(float* d, uint32_t a0, uint32_t a1,
                                         uint32_t a2, uint32_t a3,
                                         uint32_t b0, uint32_t b1) {
    asm volatile("mma.sync.aligned.m16n8k16.row.col.f32.bf16.bf16.f32 "
                 "{%0,%1,%2,%3}, {%4,%5,%6,%7}, {%8,%9}, {%0,%1,%2,%3};"
                 : "+f"(d[0]), "+f"(d[1]), "+f"(d[2]), "+f"(d[3])
                 : "r"(a0), "r"(a1), "r"(a2), "r"(a3), "r"(b0), "r"(b1));
}

__device__ __forceinline__ uint32_t bfpack(float lo, float hi) {
    __nv_bfloat162 v = __floats2bfloat162_rn(lo, hi);
    return *(uint32_t*)&v;
}

__device__ __forceinline__ void cp_async16(uint32_t dst, const void* src) {
    asm volatile("cp.async.ca.shared.global [%0], [%1], 16;" :: "r"(dst), "l"(src));
}

// quadrant smem row byte-offset for conv1-output pixel m = y*31+x
__device__ __forceinline__ uint32_t quad_row_off(int m) {
    int y = m / 31;
    int x = m - 31 * y;
    int row = ((((y & 1) << 1) | (x & 1)) << 8) + ((y >> 1) << 4) + (x >> 1);
    return (uint32_t)row * QROW;
}

// pack 27-tap fp32 vector -> 80B bf16 A row
__device__ __forceinline__ void store_a_row(char* smc, int mm, const float* v) {
    uint32_t r[16];
    #pragma unroll
    for (int i = 0; i < 13; i++) r[i] = bfpack(v[2 * i], v[2 * i + 1]);
    r[13] = bfpack(v[26], 0.f);
    r[14] = 0u; r[15] = 0u;
    uint4* dst = (uint4*)(smc + BUF0_OFF + mm * QROW);
    dst[0] = make_uint4(r[0], r[1], r[2], r[3]);
    dst[1] = make_uint4(r[4], r[5], r[6], r[7]);
    dst[2] = make_uint4(r[8], r[9], r[10], r[11]);
    dst[3] = make_uint4(r[12], r[13], r[14], r[15]);
}

// ---------------------------------------------------------------------------
// Prep kernel: convert w1/w2 into bf16 smem-image layouts once (32 blocks).
// ---------------------------------------------------------------------------
__global__ void __launch_bounds__(512)
prep_kernel(const float* __restrict__ w1, const float* __restrict__ w2)
{
    const int i = blockIdx.x * 512 + threadIdx.x;   // 16384 threads total
    if (i < 11520) {                                 // w2s u32 image
        int row = i / 20, c = i - row * 20;
        uint32_t val = 0u;
        if (c < 16) {
            int tap = row >> 6, oc = row & 63;
            int ky = tap / 3, kx = tap - 3 * ky;
            const float* ws = w2 + ((size_t)(oc * C1 + 2 * c) * 3 + ky) * 3 + kx;
            val = bfpack(ws[0], ws[9]);
        }
        ((uint32_t*)g_w2s4)[i] = val;
    }
    if (i < 640) {                                   // w1b u32 image
        int oc = i / 20, c = i - oc * 20;
        uint32_t val = 0u;
        if (c < 16) {
            float lo = (2 * c     < 27) ? w1[oc * 27 + 2 * c]     : 0.f;
            float hi = (2 * c + 1 < 27) ? w1[oc * 27 + 2 * c + 1] : 0.f;
            val = bfpack(lo, hi);
        }
        ((uint32_t*)g_w1b4)[i] = val;
    }
}

// ---------------------------------------------------------------------------
// Kernel A: per-patch CNN up to GAP. One block/patch (2048 x 512).
// conv1: im2col + mma.sync bf16.  conv2: 9 shifted GEMMs, mma.sync bf16.
// ---------------------------------------------------------------------------
__global__ void __launch_bounds__(512, 1)
patch_cnn_kernel(const float* __restrict__ img_g, const float* __restrict__ img_s,
                 const float* __restrict__ kp_g,  const float* __restrict__ kp_s,
                 const float* __restrict__ b1,    const float* __restrict__ b2)
{
    extern __shared__ char smc[];
    float* patch = (float*)(smc + PATCH_OFF);
    float* b1s   = (float*)(smc + B1S_OFF);
    float* b2s   = (float*)(smc + B2S_OFF);
    float* part  = (float*)(smc + PART_OFF);
    const uint32_t smb = smem_u32(smc);

    const int p   = blockIdx.x;
    const int set = p >> 10;
    const int m   = p & 1023;
    const int n   = m >> 2;
    const int b   = m & 3;
    const float* img = set ? img_s : img_g;
    const float* kp  = set ? kp_s  : kp_g;

    int sx = (int)floorf(kp[2 * n]     * (float)HW) - SIGMA;
    int sy = (int)floorf(kp[2 * n + 1] * (float)HW) - SIGMA;
    sx = min(max(sx, 0), HW - PATCH);
    sy = min(max(sy, 0), HW - PATCH);

    const int tid = threadIdx.x;
    const int wid = tid >> 5;
    const int lid = tid & 31;

    // ---- async weight-image copies (overlap with patch staging + im2col) ----
    #pragma unroll
    for (int i = 0; i < 6; i++) {
        int idx = tid + i * 512;
        if (idx < 2880)
            cp_async16(smb + W2S_OFF + idx * 16, &g_w2s4[idx]);
    }
    if (tid < 160)
        cp_async16(smb + W1B_OFF + tid * 16, &g_w1b4[tid]);
    asm volatile("cp.async.commit_group;" ::: "memory");

    // ---- stage patch fp32 + biases ----
    for (int i = tid; i < 3 * PATCH * PATCH; i += 512) {
        int ic = i / (PATCH * PATCH);
        int r  = i % (PATCH * PATCH);
        int y  = r / PATCH, x = r % PATCH;
        patch[ic * PPL + y * PROW + x] =
            img[(((size_t)b * 3 + ic) * HW + (sy + y)) * HW + (sx + x)];
    }
    if (tid < C1) b1s[tid] = b1[tid];
    else if (tid < C1 + C2) b2s[tid - C1] = b2[tid - C1];
    __syncthreads();

    // ---- im2col: paired pixels, A[m=y*31+x][k=ic*9+ky*3+kx] bf16, rows 80B ----
    if (tid < 496) {                      // 31 rows x 16 tasks (15 pairs + 1 single)
        const int y  = tid >> 4;
        const int jj = tid & 15;
        const int x0 = 2 * jj;
        float v0[27], v1[27];
        #pragma unroll
        for (int ic = 0; ic < 3; ic++)
            #pragma unroll
            for (int ky = 0; ky < 3; ky++) {
                const float* rp = &patch[ic * PPL + (y + ky) * PROW + x0];
                float2 a = *(const float2*)rp;
                float2 c = *(const float2*)(rp + 2);
                int k = ic * 9 + ky * 3;
                v0[k] = a.x; v0[k + 1] = a.y; v0[k + 2] = c.x;
                v1[k] = a.y; v1[k + 1] = c.x; v1[k + 2] = c.y;
            }
        const int mm = y * 31 + x0;
        store_a_row(smc, mm, v0);
        if (jj < 15) store_a_row(smc, mm + 1, v1);
    }
    asm volatile("cp.async.wait_group 0;" ::: "memory");
    __syncthreads();

    // ---- conv1 GEMM: M=1024 (961 valid), N=32, K=32; warp w -> rows 64w..64w+63
    const uint32_t a_row = (uint32_t)(lid & 15);
    const uint32_t a_kh  = (uint32_t)(lid >> 4);
    const uint32_t b_row = (uint32_t)((lid & 7) + ((lid >> 4) << 3));
    const uint32_t b_kh  = (uint32_t)((lid >> 3) & 1);

    uint32_t qv[4][4][2];
    uint32_t qoff[4][2];
    bool     qok[4][2];
    {
        uint32_t bw[2][2][4];
        #pragma unroll
        for (int ks = 0; ks < 2; ks++)
            #pragma unroll
            for (int g = 0; g < 2; g++)
                ldsm_x4(smb + W1B_OFF + (g * 16 + b_row) * QROW + b_kh * 16 + ks * 32,
                        bw[ks][g][0], bw[ks][g][1], bw[ks][g][2], bw[ks][g][3]);

        float b1c0[4], b1c1[4];
        #pragma unroll
        for (int j = 0; j < 4; j++) {
            int c0 = j * 8 + 2 * (lid & 3);
            b1c0[j] = b1s[c0];
            b1c1[j] = b1s[c0 + 1];
        }

        #pragma unroll
        for (int t = 0; t < 4; t++) {
            const int r0 = wid * 64 + t * 16;
            uint32_t a[2][4];
            #pragma unroll
            for (int ks = 0; ks < 2; ks++)
                ldsm_x4(smb + BUF0_OFF + (r0 + a_row) * QROW + a_kh * 16 + ks * 32,
                        a[ks][0], a[ks][1], a[ks][2], a[ks][3]);
            float d[4][4];
            #pragma unroll
            for (int j = 0; j < 4; j++)
                #pragma unroll
                for (int q = 0; q < 4; q++) d[j][q] = 0.0f;
            #pragma unroll
            for (int ks = 0; ks < 2; ks++)
                #pragma unroll
                for (int g = 0; g < 2; g++) {
                    mma16816(d[2 * g],     a[ks][0], a[ks][1], a[ks][2], a[ks][3],
                             bw[ks][g][0], bw[ks][g][1]);
                    mma16816(d[2 * g + 1], a[ks][0], a[ks][1], a[ks][2], a[ks][3],
                             bw[ks][g][2], bw[ks][g][3]);
                }
            const int m_lo = r0 + (lid >> 2);
            const int m_hi = m_lo + 8;
            qok[t][0]  = (m_lo < 961);
            qok[t][1]  = (m_hi < 961);
            qoff[t][0] = quad_row_off(m_lo);
            qoff[t][1] = quad_row_off(m_hi);
            #pragma unroll
            for (int j = 0; j < 4; j++) {
                qv[t][j][0] = bfpack(fmaxf(d[j][0] + b1c0[j], 0.f),
                                     fmaxf(d[j][1] + b1c1[j], 0.f));
                qv[t][j][1] = bfpack(fmaxf(d[j][2] + b1c0[j], 0.f),
                                     fmaxf(d[j][3] + b1c1[j], 0.f));
            }
        }
    }
    __syncthreads();   // all A reads done -> overwrite buf0 as quadrants

    // ---- scatter conv1 output into quadrant layout ----
    {
        const uint32_t cb = (uint32_t)(2 * (lid & 3)) * 2;
        #pragma unroll
        for (int t = 0; t < 4; t++)
            #pragma unroll
            for (int h = 0; h < 2; h++)
                if (qok[t][h]) {
                    char* base = smc + BUF0_OFF + qoff[t][h] + cb;
                    #pragma unroll
                    for (int j = 0; j < 4; j++)
                        *(uint32_t*)(base + j * 16) = qv[t][j][h];
                }
    }
    __syncthreads();

    // ---- conv2 via mma.sync: warp w = oy; 9 shifted taps ----
    float acc[8][4];
    #pragma unroll
    for (int i = 0; i < 8; i++)
        #pragma unroll
        for (int j = 0; j < 4; j++) acc[i][j] = 0.0f;

    const int w = wid;
    #pragma unroll
    for (int tap = 0; tap < 9; tap++) {
        const int ky = tap / 3, kx = tap - 3 * ky;
        const int quad = ((ky & 1) << 1) | (kx & 1);
        const int d0   = ((ky >> 1) << 4) + (kx >> 1);
        const uint32_t a_base = smb + BUF0_OFF +
            (uint32_t)(quad * 256 + w * 16 + d0 + a_row) * QROW + a_kh * 16;
        const uint32_t b_base = smb + W2S_OFF +
            (uint32_t)(tap * 64 + b_row) * QROW + b_kh * 16;

        #pragma unroll
        for (int ks = 0; ks < 2; ks++) {
            uint32_t a0, a1, a2, a3;
            ldsm_x4(a_base + ks * 32, a0, a1, a2, a3);
            #pragma unroll
            for (int ntp = 0; ntp < 4; ntp++) {
                uint32_t b0, b1r, b2r, b3;
                ldsm_x4(b_base + (uint32_t)(ntp * 16) * QROW + ks * 32, b0, b1r, b2r, b3);
                mma16816(acc[2 * ntp],     a0, a1, a2, a3, b0,  b1r);
                mma16816(acc[2 * ntp + 1], a0, a1, a2, a3, b2r, b3);
            }
        }
    }

    // ---- epilogue: relu(D + b2), mask (ox==15 | oy==15), reduce ----
    {
        const bool w_ok  = (w < C2H);
        const bool hi_ok = ((lid >> 2) != 7);
        #pragma unroll
        for (int nt = 0; nt < 8; nt++) {
            int c0 = nt * 8 + 2 * (lid & 3);
            float bb0 = b2s[c0], bb1 = b2s[c0 + 1];
            float sA = 0.0f, sB = 0.0f;
            if (w_ok) {
                sA = fmaxf(acc[nt][0] + bb0, 0.0f);
                sB = fmaxf(acc[nt][1] + bb1, 0.0f);
                if (hi_ok) {
                    sA += fmaxf(acc[nt][2] + bb0, 0.0f);
                    sB += fmaxf(acc[nt][3] + bb1, 0.0f);
                }
            }
            #pragma unroll
            for (int msk = 4; msk <= 16; msk <<= 1) {
                sA += __shfl_xor_sync(0xffffffffu, sA, msk);
                sB += __shfl_xor_sync(0xffffffffu, sB, msk);
            }
            if (lid < 4) {
                part[w * 64 + c0]     = sA;
                part[w * 64 + c0 + 1] = sB;
            }
        }
    }
    __syncthreads();

    if (tid < C2) {
        float s = 0.0f;
        #pragma unroll
        for (int ww = 0; ww < 16; ww++) s += part[ww * 64 + tid];
        g_h[((size_t)set * NPATCH + m) * C2 + tid] = s * (1.0f / 225.0f);
    }
}

// ---------------------------------------------------------------------------
// Kernel B: per-pair projected squared diff. y = wl @ (hg - hs); sum y^2.
// ---------------------------------------------------------------------------
__global__ void __launch_bounds__(128)
pair_kernel(const float* __restrict__ wl)
{
    __shared__ float d[C2];
    __shared__ float red[OUTF];
    const int pair = blockIdx.x;
    const int tid  = threadIdx.x;

    const float* hg = &g_h[(size_t)pair * C2];
    const float* hs = &g_h[((size_t)NPATCH + pair) * C2];
    if (tid < C2) d[tid] = hg[tid] - hs[tid];
    __syncthreads();

    float y = 0.0f;
    const float* wr = &wl[tid * C2];
    #pragma unroll
    for (int i = 0; i < C2; i++) y += wr[i] * d[i];
    red[tid] = y * y;
    __syncthreads();
    #pragma unroll
    for (int s = OUTF / 2; s > 0; s >>= 1) {
        if (tid < s) red[tid] += red[tid + s];
        __syncthreads();
    }
    if (tid == 0) g_pairsum[pair] = red[0];
}

// ---------------------------------------------------------------------------
// Kernel C: final deterministic reduction + mean.
// ---------------------------------------------------------------------------
__global__ void __launch_bounds__(256)
reduce_kernel(float* __restrict__ out)
{
    __shared__ float red[256];
    const int tid = threadIdx.x;
    float s = 0.0f;
    for (int i = tid; i < NPATCH; i += 256) s += g_pairsum[i];
    red[tid] = s;
    __syncthreads();
    #pragma unroll
    for (int st = 128; st > 0; st >>= 1) {
        if (tid < st) red[tid] += red[tid + st];
        __syncthreads();
    }
    if (tid == 0)
        out[0] = red[0] / (float)((size_t)NPATCH * OUTF);
}

// ---------------------------------------------------------------------------
extern "C" void kernel_launch(void* const* d_in, const int* in_sizes, int n_in,
                              void* d_out, int out_size)
{
    const float* img_g = (const float*)d_in[0];
    const float* img_s = (const float*)d_in[1];
    const float* kp_g  = (const float*)d_in[2];
    const float* kp_s  = (const float*)d_in[3];
    const float* w1    = (const float*)d_in[4];
    const float* b1    = (const float*)d_in[5];
    const float* w2    = (const float*)d_in[6];
    const float* b2    = (const float*)d_in[7];
    const float* wl    = (const float*)d_in[8];
    // d_in[9] = bl (cancels), d_in[10] = num_samples (fixed)

    cudaFuncSetAttribute(patch_cnn_kernel,
                         cudaFuncAttributeMaxDynamicSharedMemorySize, SMEM_BYTES);

    prep_kernel<<<32, 512>>>(w1, w2);
    patch_cnn_kernel<<<2 * NPATCH, 512, SMEM_BYTES>>>(img_g, img_s, kp_g, kp_s,
                                                      b1, b2);
    pair_kernel<<<NPATCH, 128>>>(wl);
    reduce_kernel<<<1, 256>>>((float*)d_out);
}

// round 10
// speedup vs baseline: 9.5522x; 1.0698x over previous
#include <cuda_runtime.h>
#include <cuda_bf16.h>
#include <cstdint>

// Fixed problem shapes
#define SIGMA   16
#define PATCH   33
#define HW      256
#define NPATCH  1024
#define C1      32
#define C1H     31
#define C2      64
#define C2H     15
#define OUTF    128

// conv1 fp32 patch staging (padded rows)
#define PROW    36
#define PPL     (PATCH * PROW)          // 1188 floats / channel

// smem byte layout
#define BUF0_OFF   0
#define QROW       80
#define BUF0_BYTES (1024 * QROW)        // 81920
#define W2S_OFF    81920                // 9*64 rows x 80B = 46080
#define PATCH_OFF  128000               // 3*1188*4 = 14256 (pad 14336)
#define W1B_OFF    142336               // 32 rows x 80B = 2560
#define B1S_OFF    144896               // 32*4
#define B2S_OFF    145024               // 64*4
#define PART_OFF   145280               // 16*64*4 = 4096
#define SMEM_BYTES 149504

__device__ float g_h[2 * NPATCH * C2];
__device__ float g_pairsum[NPATCH];
// pre-converted weight images (bf16, 80B rows) — written by prep_kernel
__device__ uint4 g_w2s4[2880];          // 46080 B
__device__ uint4 g_w1b4[160];           // 2560 B

__device__ __forceinline__ uint32_t smem_u32(const void* p) {
    uint32_t a;
    asm("{ .reg .u64 t; cvta.to.shared.u64 t, %1; cvt.u32.u64 %0, t; }" : "=r"(a) : "l"(p));
    return a;
}

__device__ __forceinline__ void ldsm_x4(uint32_t addr, uint32_t& r0, uint32_t& r1,
                                        uint32_t& r2, uint32_t& r3) {
    asm volatile("ldmatrix.sync.aligned.m8n8.x4.shared.b16 {%0,%1,%2,%3}, [%4];"
                 : "=r"(r0), "=r"(r1), "=r"(r2), "=r"(r3) : "r"(addr));
}

__device__ __forceinline__ void mma16816(float* d, uint32_t a0, uint32_t a1,
                                         uint32_t a2, uint32_t a3,
                                         uint32_t b0, uint32_t b1) {
    asm volatile("mma.sync.aligned.m16n8k16.row.col.f32.bf16.bf16.f32 "
                 "{%0,%1,%2,%3}, {%4,%5,%6,%7}, {%8,%9}, {%0,%1,%2,%3};"
                 : "+f"(d[0]), "+f"(d[1]), "+f"(d[2]), "+f"(d[3])
                 : "r"(a0), "r"(a1), "r"(a2), "r"(a3), "r"(b0), "r"(b1));
}

__device__ __forceinline__ uint32_t bfpack(float lo, float hi) {
    __nv_bfloat162 v = __floats2bfloat162_rn(lo, hi);
    return *(uint32_t*)&v;
}

__device__ __forceinline__ void cp_async16(uint32_t dst, const void* src) {
    asm volatile("cp.async.ca.shared.global [%0], [%1], 16;" :: "r"(dst), "l"(src));
}

// quadrant smem row byte-offset for conv1-output pixel m = y*31+x
__device__ __forceinline__ uint32_t quad_row_off(int m) {
    int y = m / 31;
    int x = m - 31 * y;
    int row = ((((y & 1) << 1) | (x & 1)) << 8) + ((y >> 1) << 4) + (x >> 1);
    return (uint32_t)row * QROW;
}

// pack 27-tap fp32 vector -> 64B bf16 A row (stride 80B)
__device__ __forceinline__ void store_a_row(char* smc, int mm, const float* v) {
    uint32_t r[16];
    #pragma unroll
    for (int i = 0; i < 13; i++) r[i] = bfpack(v[2 * i], v[2 * i + 1]);
    r[13] = bfpack(v[26], 0.f);
    r[14] = 0u; r[15] = 0u;
    uint4* dst = (uint4*)(smc + BUF0_OFF + mm * QROW);
    dst[0] = make_uint4(r[0], r[1], r[2], r[3]);
    dst[1] = make_uint4(r[4], r[5], r[6], r[7]);
    dst[2] = make_uint4(r[8], r[9], r[10], r[11]);
    dst[3] = make_uint4(r[12], r[13], r[14], r[15]);
}

// ---------------------------------------------------------------------------
// Prep kernel: convert w1/w2 into bf16 smem-image layouts once (32 blocks).
// ---------------------------------------------------------------------------
__global__ void __launch_bounds__(512)
prep_kernel(const float* __restrict__ w1, const float* __restrict__ w2)
{
    const int i = blockIdx.x * 512 + threadIdx.x;   // 16384 threads total
    if (i < 11520) {                                 // w2s u32 image
        int row = i / 20, c = i - row * 20;
        uint32_t val = 0u;
        if (c < 16) {
            int tap = row >> 6, oc = row & 63;
            int ky = tap / 3, kx = tap - 3 * ky;
            const float* ws = w2 + ((size_t)(oc * C1 + 2 * c) * 3 + ky) * 3 + kx;
            val = bfpack(ws[0], ws[9]);
        }
        ((uint32_t*)g_w2s4)[i] = val;
    }
    if (i < 640) {                                   // w1b u32 image
        int oc = i / 20, c = i - oc * 20;
        uint32_t val = 0u;
        if (c < 16) {
            float lo = (2 * c     < 27) ? w1[oc * 27 + 2 * c]     : 0.f;
            float hi = (2 * c + 1 < 27) ? w1[oc * 27 + 2 * c + 1] : 0.f;
            val = bfpack(lo, hi);
        }
        ((uint32_t*)g_w1b4)[i] = val;
    }
}

// ---------------------------------------------------------------------------
// Kernel A: per-patch CNN up to GAP. One block/patch (2048 x 512).
// conv1: im2col + mma.sync bf16.  conv2: 9 shifted GEMMs, mma.sync bf16,
//        m32n32 warp tiles (warp = (mg, ng)).
// ---------------------------------------------------------------------------
__global__ void __launch_bounds__(512, 1)
patch_cnn_kernel(const float* __restrict__ img_g, const float* __restrict__ img_s,
                 const float* __restrict__ kp_g,  const float* __restrict__ kp_s,
                 const float* __restrict__ b1,    const float* __restrict__ b2)
{
    extern __shared__ char smc[];
    float* patch = (float*)(smc + PATCH_OFF);
    float* b1s   = (float*)(smc + B1S_OFF);
    float* b2s   = (float*)(smc + B2S_OFF);
    float* part  = (float*)(smc + PART_OFF);
    const uint32_t smb = smem_u32(smc);

    const int p   = blockIdx.x;
    const int set = p >> 10;
    const int m   = p & 1023;
    const int n   = m >> 2;
    const int b   = m & 3;
    const float* img = set ? img_s : img_g;
    const float* kp  = set ? kp_s  : kp_g;

    int sx = (int)floorf(kp[2 * n]     * (float)HW) - SIGMA;
    int sy = (int)floorf(kp[2 * n + 1] * (float)HW) - SIGMA;
    sx = min(max(sx, 0), HW - PATCH);
    sy = min(max(sy, 0), HW - PATCH);

    const int tid = threadIdx.x;
    const int wid = tid >> 5;
    const int lid = tid & 31;

    // ---- async weight-image copies (overlap with patch staging + im2col) ----
    #pragma unroll
    for (int i = 0; i < 6; i++) {
        int idx = tid + i * 512;
        if (idx < 2880)
            cp_async16(smb + W2S_OFF + idx * 16, &g_w2s4[idx]);
    }
    if (tid < 160)
        cp_async16(smb + W1B_OFF + tid * 16, &g_w1b4[tid]);
    asm volatile("cp.async.commit_group;" ::: "memory");

    // ---- stage patch fp32 + biases ----
    for (int i = tid; i < 3 * PATCH * PATCH; i += 512) {
        int ic = i / (PATCH * PATCH);
        int r  = i % (PATCH * PATCH);
        int y  = r / PATCH, x = r % PATCH;
        patch[ic * PPL + y * PROW + x] =
            img[(((size_t)b * 3 + ic) * HW + (sy + y)) * HW + (sx + x)];
    }
    if (tid < C1) b1s[tid] = b1[tid];
    else if (tid < C1 + C2) b2s[tid - C1] = b2[tid - C1];
    __syncthreads();

    // ---- im2col 2x2 blocks: A[m=y*31+x][k=ic*9+ky*3+kx] bf16, rows 80B ----
    if (tid < 256) {
        const int by = tid >> 4, bx = tid & 15;
        const int y0 = 2 * by, x0 = 2 * bx;
        const bool y1v = (y0 + 1 < C1H);
        const bool x1v = (x0 + 1 < C1H);

        float ld[3][4][4];
        #pragma unroll
        for (int ic = 0; ic < 3; ic++)
            #pragma unroll
            for (int r = 0; r < 4; r++)
                if (r < 3 || y1v) {
                    const float* rp = &patch[ic * PPL + (y0 + r) * PROW + x0];
                    float2 a = *(const float2*)rp;
                    float2 c = *(const float2*)(rp + 2);
                    ld[ic][r][0] = a.x; ld[ic][r][1] = a.y;
                    ld[ic][r][2] = c.x; ld[ic][r][3] = c.y;
                }

        #pragma unroll
        for (int dy = 0; dy < 2; dy++) {
            if (dy == 1 && !y1v) break;
            #pragma unroll
            for (int dx = 0; dx < 2; dx++) {
                if (dx == 1 && !x1v) break;
                float v[27];
                #pragma unroll
                for (int ic = 0; ic < 3; ic++)
                    #pragma unroll
                    for (int ky = 0; ky < 3; ky++)
                        #pragma unroll
                        for (int kx = 0; kx < 3; kx++)
                            v[ic * 9 + ky * 3 + kx] = ld[ic][ky + dy][kx + dx];
                store_a_row(smc, (y0 + dy) * 31 + (x0 + dx), v);
            }
        }
    }
    asm volatile("cp.async.wait_group 0;" ::: "memory");
    __syncthreads();

    // ---- conv1 GEMM: M=1024 (961 valid), N=32, K=32; warp w -> rows 64w..64w+63
    const uint32_t a_row = (uint32_t)(lid & 15);
    const uint32_t a_kh  = (uint32_t)(lid >> 4);
    const uint32_t b_row = (uint32_t)((lid & 7) + ((lid >> 4) << 3));
    const uint32_t b_kh  = (uint32_t)((lid >> 3) & 1);

    uint32_t qv[4][4][2];
    uint32_t qoff[4][2];
    bool     qok[4][2];
    {
        uint32_t bw[2][2][4];
        #pragma unroll
        for (int ks = 0; ks < 2; ks++)
            #pragma unroll
            for (int g = 0; g < 2; g++)
                ldsm_x4(smb + W1B_OFF + (g * 16 + b_row) * QROW + b_kh * 16 + ks * 32,
                        bw[ks][g][0], bw[ks][g][1], bw[ks][g][2], bw[ks][g][3]);

        float b1c0[4], b1c1[4];
        #pragma unroll
        for (int j = 0; j < 4; j++) {
            int c0 = j * 8 + 2 * (lid & 3);
            b1c0[j] = b1s[c0];
            b1c1[j] = b1s[c0 + 1];
        }

        #pragma unroll
        for (int t = 0; t < 4; t++) {
            const int r0 = wid * 64 + t * 16;
            uint32_t a[2][4];
            #pragma unroll
            for (int ks = 0; ks < 2; ks++)
                ldsm_x4(smb + BUF0_OFF + (r0 + a_row) * QROW + a_kh * 16 + ks * 32,
                        a[ks][0], a[ks][1], a[ks][2], a[ks][3]);
            float d[4][4];
            #pragma unroll
            for (int j = 0; j < 4; j++)
                #pragma unroll
                for (int q = 0; q < 4; q++) d[j][q] = 0.0f;
            #pragma unroll
            for (int ks = 0; ks < 2; ks++)
                #pragma unroll
                for (int g = 0; g < 2; g++) {
                    mma16816(d[2 * g],     a[ks][0], a[ks][1], a[ks][2], a[ks][3],
                             bw[ks][g][0], bw[ks][g][1]);
                    mma16816(d[2 * g + 1], a[ks][0], a[ks][1], a[ks][2], a[ks][3],
                             bw[ks][g][2], bw[ks][g][3]);
                }
            const int m_lo = r0 + (lid >> 2);
            const int m_hi = m_lo + 8;
            qok[t][0]  = (m_lo < 961);
            qok[t][1]  = (m_hi < 961);
            qoff[t][0] = quad_row_off(m_lo);
            qoff[t][1] = quad_row_off(m_hi);
            #pragma unroll
            for (int j = 0; j < 4; j++) {
                qv[t][j][0] = bfpack(fmaxf(d[j][0] + b1c0[j], 0.f),
                                     fmaxf(d[j][1] + b1c1[j], 0.f));
                qv[t][j][1] = bfpack(fmaxf(d[j][2] + b1c0[j], 0.f),
                                     fmaxf(d[j][3] + b1c1[j], 0.f));
            }
        }
    }
    __syncthreads();   // all A reads done -> overwrite buf0 as quadrants

    // ---- scatter conv1 output into quadrant layout ----
    {
        const uint32_t cb = (uint32_t)(2 * (lid & 3)) * 2;
        #pragma unroll
        for (int t = 0; t < 4; t++)
            #pragma unroll
            for (int h = 0; h < 2; h++)
                if (qok[t][h]) {
                    char* base = smc + BUF0_OFF + qoff[t][h] + cb;
                    #pragma unroll
                    for (int j = 0; j < 4; j++)
                        *(uint32_t*)(base + j * 16) = qv[t][j][h];
                }
    }
    __syncthreads();

    // ---- conv2 via mma.sync: m32n32 warp tiles; warp = (mg 0..7, ng 0..1) ----
    float acc[2][4][4];
    #pragma unroll
    for (int t = 0; t < 2; t++)
        #pragma unroll
        for (int j = 0; j < 4; j++)
            #pragma unroll
            for (int q = 0; q < 4; q++) acc[t][j][q] = 0.0f;

    const int mg = wid & 7;
    const int ng = wid >> 3;

    #pragma unroll
    for (int tap = 0; tap < 9; tap++) {
        const int ky = tap / 3, kx = tap - 3 * ky;
        const int quad = ((ky & 1) << 1) | (kx & 1);
        const int d0   = ((ky >> 1) << 4) + (kx >> 1);
        const uint32_t a_base0 = smb + BUF0_OFF +
            (uint32_t)(quad * 256 + (2 * mg) * 16 + d0 + a_row) * QROW + a_kh * 16;
        const uint32_t a_base1 = a_base0 + 16 * QROW;
        const uint32_t b_base  = smb + W2S_OFF +
            (uint32_t)(tap * 64 + 2 * ng * 16 + b_row) * QROW + b_kh * 16;

        #pragma unroll
        for (int ks = 0; ks < 2; ks++) {
            uint32_t a0[4], a1[4];
            ldsm_x4(a_base0 + ks * 32, a0[0], a0[1], a0[2], a0[3]);
            ldsm_x4(a_base1 + ks * 32, a1[0], a1[1], a1[2], a1[3]);
            uint32_t b0[4], b1r[4];
            ldsm_x4(b_base + ks * 32, b0[0], b0[1], b0[2], b0[3]);
            ldsm_x4(b_base + 16 * QROW + ks * 32, b1r[0], b1r[1], b1r[2], b1r[3]);

            mma16816(acc[0][0], a0[0], a0[1], a0[2], a0[3], b0[0],  b0[1]);
            mma16816(acc[0][1], a0[0], a0[1], a0[2], a0[3], b0[2],  b0[3]);
            mma16816(acc[0][2], a0[0], a0[1], a0[2], a0[3], b1r[0], b1r[1]);
            mma16816(acc[0][3], a0[0], a0[1], a0[2], a0[3], b1r[2], b1r[3]);
            mma16816(acc[1][0], a1[0], a1[1], a1[2], a1[3], b0[0],  b0[1]);
            mma16816(acc[1][1], a1[0], a1[1], a1[2], a1[3], b0[2],  b0[3]);
            mma16816(acc[1][2], a1[0], a1[1], a1[2], a1[3], b1r[0], b1r[1]);
            mma16816(acc[1][3], a1[0], a1[1], a1[2], a1[3], b1r[2], b1r[3]);
        }
    }

    // ---- epilogue: relu(D + b2), mask (ox==15 | oy==15), reduce ----
    {
        const bool hi_ok = ((lid >> 2) != 7);
        #pragma unroll
        for (int t = 0; t < 2; t++) {
            const int oy = 2 * mg + t;
            const bool oy_ok = (oy < C2H);
            #pragma unroll
            for (int j = 0; j < 4; j++) {
                int c0 = ng * 32 + j * 8 + 2 * (lid & 3);
                float bb0 = b2s[c0], bb1 = b2s[c0 + 1];
                float sA = 0.0f, sB = 0.0f;
                if (oy_ok) {
                    sA = fmaxf(acc[t][j][0] + bb0, 0.0f);
                    sB = fmaxf(acc[t][j][1] + bb1, 0.0f);
                    if (hi_ok) {
                        sA += fmaxf(acc[t][j][2] + bb0, 0.0f);
                        sB += fmaxf(acc[t][j][3] + bb1, 0.0f);
                    }
                }
                #pragma unroll
                for (int msk = 4; msk <= 16; msk <<= 1) {
                    sA += __shfl_xor_sync(0xffffffffu, sA, msk);
                    sB += __shfl_xor_sync(0xffffffffu, sB, msk);
                }
                if (lid < 4) {
                    part[oy * 64 + c0]     = sA;
                    part[oy * 64 + c0 + 1] = sB;
                }
            }
        }
    }
    __syncthreads();

    if (tid < C2) {
        float s = 0.0f;
        #pragma unroll
        for (int ww = 0; ww < 16; ww++) s += part[ww * 64 + tid];
        g_h[((size_t)set * NPATCH + m) * C2 + tid] = s * (1.0f / 225.0f);
    }
}

// ---------------------------------------------------------------------------
// Kernel B: per-pair projected squared diff. y = wl @ (hg - hs); sum y^2.
// ---------------------------------------------------------------------------
__global__ void __launch_bounds__(128)
pair_kernel(const float* __restrict__ wl)
{
    __shared__ float d[C2];
    __shared__ float red[OUTF];
    const int pair = blockIdx.x;
    const int tid  = threadIdx.x;

    const float* hg = &g_h[(size_t)pair * C2];
    const float* hs = &g_h[((size_t)NPATCH + pair) * C2];
    if (tid < C2) d[tid] = hg[tid] - hs[tid];
    __syncthreads();

    float y = 0.0f;
    const float* wr = &wl[tid * C2];
    #pragma unroll
    for (int i = 0; i < C2; i++) y += wr[i] * d[i];
    red[tid] = y * y;
    __syncthreads();
    #pragma unroll
    for (int s = OUTF / 2; s > 0; s >>= 1) {
        if (tid < s) red[tid] += red[tid + s];
        __syncthreads();
    }
    if (tid == 0) g_pairsum[pair] = red[0];
}

// ---------------------------------------------------------------------------
// Kernel C: final deterministic reduction + mean.
// ---------------------------------------------------------------------------
__global__ void __launch_bounds__(256)
reduce_kernel(float* __restrict__ out)
{
    __shared__ float red[256];
    const int tid = threadIdx.x;
    float s = 0.0f;
    for (int i = tid; i < NPATCH; i += 256) s += g_pairsum[i];
    red[tid] = s;
    __syncthreads();
    #pragma unroll
    for (int st = 128; st > 0; st >>= 1) {
        if (tid < st) red[tid] += red[tid + st];
        __syncthreads();
    }
    if (tid == 0)
        out[0] = red[0] / (float)((size_t)NPATCH * OUTF);
}

// ---------------------------------------------------------------------------
extern "C" void kernel_launch(void* const* d_in, const int* in_sizes, int n_in,
                              void* d_out, int out_size)
{
    const float* img_g = (const float*)d_in[0];
    const float* img_s = (const float*)d_in[1];
    const float* kp_g  = (const float*)d_in[2];
    const float* kp_s  = (const float*)d_in[3];
    const float* w1    = (const float*)d_in[4];
    const float* b1    = (const float*)d_in[5];
    const float* w2    = (const float*)d_in[6];
    const float* b2    = (const float*)d_in[7];
    const float* wl    = (const float*)d_in[8];
    // d_in[9] = bl (cancels), d_in[10] = num_samples (fixed)

    cudaFuncSetAttribute(patch_cnn_kernel,
                         cudaFuncAttributeMaxDynamicSharedMemorySize, SMEM_BYTES);

    prep_kernel<<<32, 512>>>(w1, w2);
    patch_cnn_kernel<<<2 * NPATCH, 512, SMEM_BYTES>>>(img_g, img_s, kp_g, kp_s,
                                                      b1, b2);
    pair_kernel<<<NPATCH, 128>>>(wl);
    reduce_kernel<<<1, 256>>>((float*)d_out);
}